// round 17
// baseline (speedup 1.0000x reference)
#include <cuda_runtime.h>
#include <cstdint>

// Sparse transposed conv: gather-GEMM-scatter over rulebook.
// x:[N_SRC,32] f32, weight:[K,32,16] f32, src/dst:[K,M] i32, out:[N_TGT,16] f32.
// v16 = v14 champion (cp.async staged gather, 4-lane-per-pair, f32x2 FMA,
//       register-direct red.v4 scatter, FULL-templated tails) + 2 sequential
//       tiles per block in ONE buffer, ordered so tile1's staging overlaps
//       tile0's scatter:  stage0 | compute0 | stage1 ; scatter0 | wait1 |
//       compute1 | scatter1.  Same 34KB smem, 4 blocks/SM.

#define CIN   32
#define COUT  16
#define TPB   256
#define PPB   256                 // pairs per tile
#define TILES 2
#define NITER ((PPB * 8) / TPB)   // 8 cp.async (16B) per thread per tile

typedef unsigned long long ull;
typedef unsigned int       u32;

#define FMA2(acc, a, b) \
    asm("fma.rn.f32x2 %0, %1, %2, %0;" : "+l"(acc) : "l"(a), "l"(b))

#define UNPACK2(lo, hi, v) \
    asm("mov.b64 {%0, %1}, %2;" : "=f"(lo), "=f"(hi) : "l"(v))

// dynamic smem: [0,2048) wsm (f32x2-interleaved), [2048,+32K) xsm staging
#define XSM_OFF 2048
#define SMEM_BYTES (XSM_OFF + PPB * 8 * 16)   // 34816

// ---- stage one tile's 256 rows into the shared buffer (cp.async) ----
template <bool FULL>
__device__ __forceinline__
void stage_tile(const float* __restrict__ x, const int* __restrict__ src_idx,
                long long kb, int npair, u32 xsm_base)
{
    #pragma unroll
    for (int i = 0; i < NITER; i++) {
        int idx = i * TPB + threadIdx.x;
        int r = idx >> 3, j = idx & 7;
        int rc = FULL ? r : ((r < npair) ? r : 0);
        int s = __ldg(src_idx + kb + rc);
        const float4* src = reinterpret_cast<const float4*>(x) + (size_t)s * 8 + j;
        u32 dst = xsm_base + (u32)(r * 8 + (j ^ ((r >> 2) & 7))) * 16;
        asm volatile("cp.async.cg.shared.global [%0], [%1], 16;"
                     :: "r"(dst), "l"(src));
    }
    asm volatile("cp.async.commit_group;");
}

// ---- compute one tile from the shared buffer into acc ----
__device__ __forceinline__
void compute_tile(const char* smem, int g, int l, ull acc[4][4])
{
    const float4*    xsm  = (const float4*)(smem + XSM_OFF);
    const longlong2* wsm2 = (const longlong2*)smem;
    const int sw = g & 7;

    #pragma unroll
    for (int ii = 0; ii < 4; ii++)
        #pragma unroll
        for (int m = 0; m < 4; m++) acc[ii][m] = 0ull;

    #pragma unroll
    for (int jj = 0; jj < 8; jj++) {
        const longlong2 wa0 = wsm2[(2 * jj) * 8 + 2 * l];
        const longlong2 wa1 = wsm2[(2 * jj) * 8 + 2 * l + 1];
        const longlong2 wb0 = wsm2[(2 * jj + 1) * 8 + 2 * l];
        const longlong2 wb1 = wsm2[(2 * jj + 1) * 8 + 2 * l + 1];
        #pragma unroll
        for (int ii = 0; ii < 4; ii++) {
            const int r = g * 4 + ii;
            longlong2 xv = *(const longlong2*)&xsm[r * 8 + (jj ^ sw)];
            const ull xlo = (ull)xv.x;      // channels 4jj, 4jj+1
            const ull xhi = (ull)xv.y;      // channels 4jj+2, 4jj+3
            FMA2(acc[ii][0], xlo, (ull)wa0.x);
            FMA2(acc[ii][1], xlo, (ull)wa0.y);
            FMA2(acc[ii][2], xlo, (ull)wa1.x);
            FMA2(acc[ii][3], xlo, (ull)wa1.y);
            FMA2(acc[ii][0], xhi, (ull)wb0.x);
            FMA2(acc[ii][1], xhi, (ull)wb0.y);
            FMA2(acc[ii][2], xhi, (ull)wb1.x);
            FMA2(acc[ii][3], xhi, (ull)wb1.y);
        }
    }
}

// ---- scatter one tile's accumulators (register-direct red.v4) ----
template <bool FULL>
__device__ __forceinline__
void scatter_tile(float* __restrict__ out, const int dsts[4], int l, ull acc[4][4])
{
    #pragma unroll
    for (int ii = 0; ii < 4; ii++) {
        if (!FULL && dsts[ii] < 0) continue;
        float l0, h0, l1, h1, l2, h2, l3, h3;
        UNPACK2(l0, h0, acc[ii][0]);
        UNPACK2(l1, h1, acc[ii][1]);
        UNPACK2(l2, h2, acc[ii][2]);
        UNPACK2(l3, h3, acc[ii][3]);
        float* o = out + (size_t)dsts[ii] * COUT + 4 * l;
        asm volatile("red.global.add.v4.f32 [%0], {%1, %2, %3, %4};"
                     :: "l"(o),
                        "f"(l0 + h0), "f"(l1 + h1),
                        "f"(l2 + h2), "f"(l3 + h3) : "memory");
    }
}

template <bool FULL>
__device__ __forceinline__
void block_body(const float* __restrict__ x,
                const float* __restrict__ w,
                const int*   __restrict__ src_idx,
                const int*   __restrict__ dst_idx,
                float*       __restrict__ out,
                char* smem, u32 xsm_base,
                long long kb0, int np0, int np1, int k)
{
    float* wsm = (float*)smem;
    const long long kb1 = kb0 + PPB;
    const int g = threadIdx.x >> 2;
    const int l = threadIdx.x & 3;

    // stage tile 0
    stage_tile<FULL>(x, src_idx, kb0, np0, xsm_base);

    // weight[k] -> smem once, interleaved: word = cp*32 + j*2 + (c&1)
    const float* wk = w + (size_t)k * (CIN * COUT);
    #pragma unroll
    for (int i = 0; i < (CIN * COUT) / TPB; i++) {
        int t = i * TPB + threadIdx.x;
        int c = t >> 4, j = t & 15;
        wsm[(c >> 1) * 32 + j * 2 + (c & 1)] = __ldg(wk + t);
    }

    // dst indices for both tiles (L2-resident, overlap with staging)
    int d0[4], d1[4];
    #pragma unroll
    for (int ii = 0; ii < 4; ii++) {
        int r = g * 4 + ii;
        d0[ii] = (FULL || r < np0) ? __ldg(dst_idx + kb0 + r) : -1;
        d1[ii] = (FULL || r < np1) ? __ldg(dst_idx + kb1 + r) : -1;
    }

    asm volatile("cp.async.wait_group 0;");
    __syncthreads();

    // compute tile 0
    ull acc[4][4];
    compute_tile(smem, g, l, acc);

    __syncthreads();                       // buffer reads done

    // stage tile 1 (async) BEFORE scatter 0: REDs hide the gather latency
    if (FULL || np1 > 0) {
        stage_tile<FULL>(x, src_idx, kb1, np1, xsm_base);
        scatter_tile<FULL>(out, d0, l, acc);

        asm volatile("cp.async.wait_group 0;");
        __syncthreads();

        compute_tile(smem, g, l, acc);
        scatter_tile<FULL>(out, d1, l, acc);
    } else {
        scatter_tile<FULL>(out, d0, l, acc);
    }
}

__global__ __launch_bounds__(TPB, 4)
void rulebook_gemm_scatter(const float* __restrict__ x,
                           const float* __restrict__ w,
                           const int*   __restrict__ src_idx,
                           const int*   __restrict__ dst_idx,
                           float*       __restrict__ out,
                           int M)
{
    extern __shared__ char smem[];

    const int k  = blockIdx.y;
    const int pb = blockIdx.x * (PPB * TILES);
    const int np0 = min(PPB, M - pb);
    const int np1 = min(PPB, M - (pb + PPB));
    const long long kb0 = (long long)k * M + pb;

    u32 xsm_base;
    asm("{ .reg .u64 t; cvta.to.shared.u64 t, %1; cvt.u32.u64 %0, t; }"
        : "=r"(xsm_base) : "l"(smem + XSM_OFF));

    if (np0 == PPB && np1 == PPB) {
        block_body<true >(x, w, src_idx, dst_idx, out, smem, xsm_base, kb0, np0, np1, k);
    } else {
        block_body<false>(x, w, src_idx, dst_idx, out, smem, xsm_base, kb0, np0, np1, k);
    }
}

extern "C" void kernel_launch(void* const* d_in, const int* in_sizes, int n_in,
                              void* d_out, int out_size)
{
    const float* x       = (const float*)d_in[0];
    const float* weight  = (const float*)d_in[1];
    const int*   src_idx = (const int*)d_in[2];
    const int*   dst_idx = (const int*)d_in[3];
    float*       out     = (float*)d_out;

    const int K = in_sizes[1] / (CIN * COUT);   // 27
    const int M = in_sizes[2] / K;              // 200000

    cudaMemsetAsync(d_out, 0, (size_t)out_size * sizeof(float), 0);

    cudaFuncSetAttribute(rulebook_gemm_scatter,
                         cudaFuncAttributeMaxDynamicSharedMemorySize, SMEM_BYTES);

    const int span = PPB * TILES;               // 512 pairs per block
    dim3 grid((M + span - 1) / span, K);
    rulebook_gemm_scatter<<<grid, TPB, SMEM_BYTES>>>(x, weight, src_idx, dst_idx, out, M);
}